// round 2
// baseline (speedup 1.0000x reference)
#include <cuda_runtime.h>

#define NN 50000
#define FF 64
#define HIDN 32
#define TT 8
#define EE 800000
#define PP 800000

// ---------------- persistent scratch (static device arrays; no allocation) ---
__device__ float g_ACAT[(size_t)NN * 224];   // [tx1(64) | u=L tx1(64) | H(32) | th1(32) | uh(32)]
__device__ float g_Z0[(size_t)NN * 128];     // x@(Wx0-Wx2) + (bx+bh+b_gate)
__device__ float g_PRE[(size_t)NN * 128];    // gate preactivations
__device__ float g_TX1[(size_t)NN * 64];
__device__ float g_TH1[(size_t)NN * 32];
__device__ float g_H[(size_t)NN * 32];
__device__ float g_C[(size_t)NN * 32];
__device__ float g_dis[NN];
__device__ int   g_deg[NN];
__device__ int   g_hist[NN];
__device__ int   g_fill[NN];
__device__ int   g_cs[NN + 1];
__device__ int   g_erow[EE];
__device__ float g_enorm[EE];
__device__ float g_B[224 * 128];
__device__ float g_W03[64 * 128];
__device__ float g_biasT[128];
__device__ float g_h1[(size_t)NN * 16];

__device__ __forceinline__ float sigm(float v) { return 1.0f / (1.0f + expf(-v)); }

// ---------------- weight folding --------------------------------------------
// B rows: [0:64)=Wx1  [64:128)=2*Wx2  [128:160)=Wh0-Wh2  [160:192)=Wh1  [192:224)=2*Wh2
// W03[f][j] = Wx0 - Wx2 ;  biasT[j] = bx + bh + b_gate
__global__ void build_weights(const float* __restrict__ Wx, const float* __restrict__ bx,
                              const float* __restrict__ Wh, const float* __restrict__ bh,
                              const float* __restrict__ bg) {
    int idx = blockIdx.x * blockDim.x + threadIdx.x;
    const int NB = 224 * 128;
    if (idx < NB) {
        int r = idx >> 7, j = idx & 127;
        int g = j >> 5, h = j & 31;
        float v;
        if (r < 64)        v = Wx[((g * 3 + 1) * 64 + r) * 32 + h];
        else if (r < 128)  v = 2.0f * Wx[((g * 3 + 2) * 64 + (r - 64)) * 32 + h];
        else if (r < 160)  v = Wh[((g * 3 + 0) * 32 + (r - 128)) * 32 + h]
                             - Wh[((g * 3 + 2) * 32 + (r - 128)) * 32 + h];
        else if (r < 192)  v = Wh[((g * 3 + 1) * 32 + (r - 160)) * 32 + h];
        else               v = 2.0f * Wh[((g * 3 + 2) * 32 + (r - 192)) * 32 + h];
        g_B[idx] = v;
    } else if (idx < NB + 64 * 128) {
        int k = idx - NB;
        int f = k >> 7, j = k & 127;
        int g = j >> 5, h = j & 31;
        g_W03[k] = Wx[((g * 3 + 0) * 64 + f) * 32 + h] - Wx[((g * 3 + 2) * 64 + f) * 32 + h];
    } else if (idx < NB + 64 * 128 + 128) {
        int j = idx - NB - 64 * 128;
        g_biasT[j] = bx[j] + bh[j] + bg[j];
    }
}

__global__ void zero_state() {
    int idx = blockIdx.x * blockDim.x + threadIdx.x;
    if (idx < NN * HIDN) {
        g_H[idx] = 0.0f;
        g_C[idx] = 0.0f;
        int n = idx >> 5, h = idx & 31;
        g_ACAT[(size_t)n * 224 + 128 + h] = 0.0f;
    }
}

__global__ void zero_counts() {
    int n = blockIdx.x * blockDim.x + threadIdx.x;
    if (n < NN) { g_deg[n] = 0; g_hist[n] = 0; g_fill[n] = 0; }
}

__global__ void histogram_kernel(const int* __restrict__ row, const int* __restrict__ col) {
    int e = blockIdx.x * blockDim.x + threadIdx.x;
    if (e < EE) {
        atomicAdd(&g_deg[row[e]], 1);
        atomicAdd(&g_hist[col[e]], 1);
    }
}

__global__ void dis_kernel() {
    int n = blockIdx.x * blockDim.x + threadIdx.x;
    if (n < NN) {
        int d = g_deg[n];
        g_dis[n] = (d > 0) ? rsqrtf((float)d) : 0.0f;
    }
}

// single-block exclusive scan of g_hist -> g_cs (N+1 entries)
__global__ void scan_kernel() {
    __shared__ int sh[1024];
    __shared__ int stotal;
    int tid = threadIdx.x;
    if (tid == 0) stotal = 0;
    __syncthreads();
    for (int base = 0; base < NN; base += 1024) {
        int i = base + tid;
        int v = (i < NN) ? g_hist[i] : 0;
        sh[tid] = v;
        __syncthreads();
        for (int off = 1; off < 1024; off <<= 1) {
            int t = 0;
            if (tid >= off) t = sh[tid - off];
            __syncthreads();
            sh[tid] += t;
            __syncthreads();
        }
        if (i < NN) g_cs[i] = stotal + sh[tid] - v;
        __syncthreads();
        if (tid == 0) stotal += sh[1023];
        __syncthreads();
    }
    if (tid == 0) g_cs[NN] = stotal;
}

__global__ void scatter_kernel(const int* __restrict__ row, const int* __restrict__ col) {
    int e = blockIdx.x * blockDim.x + threadIdx.x;
    if (e < EE) {
        int r = row[e], c = col[e];
        int pos = g_cs[c] + atomicAdd(&g_fill[c], 1);
        g_erow[pos] = r;
        g_enorm[pos] = -g_dis[r] * g_dis[c];
    }
}

// one warp per destination node; gathers over incoming (CSC) edges.
// level 0: sources x (64) + H (32) -> TX1/TH1 + ACAT cols {0..63,160..191}
// level 1: sources TX1 + TH1      -> ACAT cols {64..127,192..223}
__global__ void gather_kernel(const float* __restrict__ xsrc, int level) {
    int warp = (blockIdx.x * blockDim.x + threadIdx.x) >> 5;
    int lane = threadIdx.x & 31;
    if (warp >= NN) return;
    int s = g_cs[warp], e = g_cs[warp + 1];
    const float* __restrict__ X = level ? g_TX1 : xsrc;
    const float* __restrict__ Hb = level ? g_TH1 : g_H;
    float a0 = 0.0f, a1 = 0.0f, ah = 0.0f;
#pragma unroll 4
    for (int i = s; i < e; i++) {
        int r = g_erow[i];
        float w = g_enorm[i];
        a0 += w * X[(size_t)r * 64 + lane];
        a1 += w * X[(size_t)r * 64 + 32 + lane];
        ah += w * Hb[(size_t)r * 32 + lane];
    }
    float* acat = g_ACAT + (size_t)warp * 224;
    if (level == 0) {
        g_TX1[(size_t)warp * 64 + lane] = a0;
        g_TX1[(size_t)warp * 64 + 32 + lane] = a1;
        g_TH1[(size_t)warp * 32 + lane] = ah;
        acat[lane] = a0;
        acat[32 + lane] = a1;
        acat[160 + lane] = ah;
    } else {
        acat[64 + lane] = a0;
        acat[96 + lane] = a1;
        acat[192 + lane] = ah;
    }
}

// C[n][0:128] = init + A[n][0:K] @ Bm   (BM=64, BN=128, BK=8; 256 threads; 4x8 per thread)
// mode 0: A=x (lda=64,K=64),  Bm=g_W03, init=g_biasT[col], out=g_Z0
// mode 1: A=g_ACAT (lda=224,K=224), Bm=g_B, init=g_Z0[row], out=g_PRE
__global__ void gemm128(const float* __restrict__ Aext, int mode) {
    const float* A; int lda, K; const float* Bm; float* Cout;
    if (mode == 0) { A = Aext;   lda = 64;  K = 64;  Bm = g_W03; Cout = g_Z0; }
    else           { A = g_ACAT; lda = 224; K = 224; Bm = g_B;   Cout = g_PRE; }

    __shared__ float As[8][64];
    __shared__ float Bs[8][128];
    int bm = blockIdx.x * 64;
    int tid = threadIdx.x;
    int tcol = tid & 15;   // 16 col-groups * 8 cols
    int trow = tid >> 4;   // 16 row-groups * 4 rows
    float acc[4][8];
#pragma unroll
    for (int i = 0; i < 4; i++)
#pragma unroll
        for (int j = 0; j < 8; j++) acc[i][j] = 0.0f;

    for (int k0 = 0; k0 < K; k0 += 8) {
#pragma unroll
        for (int i = 0; i < 2; i++) {
            int idx = tid + i * 256;       // 512 elems
            int m = idx >> 3, k = idx & 7;
            int row = bm + m;
            As[k][m] = (row < NN) ? A[(size_t)row * lda + k0 + k] : 0.0f;
        }
#pragma unroll
        for (int i = 0; i < 4; i++) {
            int idx = tid + i * 256;       // 1024 elems
            int k = idx >> 7, n = idx & 127;
            Bs[k][n] = Bm[(size_t)(k0 + k) * 128 + n];
        }
        __syncthreads();
#pragma unroll
        for (int k = 0; k < 8; k++) {
            float a[4], b[8];
#pragma unroll
            for (int i = 0; i < 4; i++) a[i] = As[k][trow * 4 + i];
#pragma unroll
            for (int j = 0; j < 8; j++) b[j] = Bs[k][tcol * 8 + j];
#pragma unroll
            for (int i = 0; i < 4; i++)
#pragma unroll
                for (int j = 0; j < 8; j++) acc[i][j] += a[i] * b[j];
        }
        __syncthreads();
    }
#pragma unroll
    for (int i = 0; i < 4; i++) {
        int row = bm + trow * 4 + i;
        if (row < NN) {
#pragma unroll
            for (int j = 0; j < 8; j++) {
                int n = tcol * 8 + j;
                float v = acc[i][j];
                if (mode == 0) v += g_biasT[n];
                else           v += g_Z0[(size_t)row * 128 + n];
                Cout[(size_t)row * 128 + n] = v;
            }
        }
    }
}

__global__ void gates_kernel(const float* __restrict__ wc) {
    int idx = blockIdx.x * blockDim.x + threadIdx.x;
    if (idx < NN * HIDN) {
        int n = idx >> 5, h = idx & 31;
        const float* pre = g_PRE + (size_t)n * 128;
        float Cs = g_C[idx];
        float ig = sigm(pre[h]       + wc[h]      * Cs);
        float fg = sigm(pre[32 + h]  + wc[32 + h] * Cs);
        float ct = tanhf(pre[64 + h]);
        float Cn = fg * Cs + ig * ct;
        float og = sigm(pre[96 + h] + wc[64 + h] * Cn);
        float Hn = og * tanhf(Cn);
        g_C[idx] = Cn;
        g_H[idx] = Hn;
        g_ACAT[(size_t)n * 224 + 128 + h] = Hn;
    }
}

__global__ void h1_kernel(const float* __restrict__ w, const float* __restrict__ b) {
    int idx = blockIdx.x * blockDim.x + threadIdx.x;
    if (idx < NN * 16) {
        int n = idx >> 4, o = idx & 15;
        float s = b[o];
        const float* hr = g_H + (size_t)n * 32;
#pragma unroll
        for (int k = 0; k < 32; k++) {
            float hv = hr[k];
            hv = hv > 0.0f ? hv : 0.0f;
            s += hv * w[k * 16 + o];
        }
        g_h1[idx] = s > 0.0f ? s : 0.0f;
    }
}

__global__ void pair_kernel(const int* __restrict__ src, const int* __restrict__ dst,
                            const float* __restrict__ fc2w, const float* __restrict__ fc2b,
                            const float* __restrict__ fc3w, const float* __restrict__ fc3b,
                            const float* __restrict__ bfw, const float* __restrict__ bfb,
                            float* __restrict__ out) {
    __shared__ float sw2[512], sb2[16], sw3[128], sb3[8], swb[8];
    __shared__ float sbb;
    int t = threadIdx.x;
    sw2[t] = fc2w[t];
    sw2[t + 256] = fc2w[t + 256];
    if (t < 128) sw3[t] = fc3w[t];
    if (t < 16) sb2[t] = fc2b[t];
    if (t < 8) { sb3[t] = fc3b[t]; swb[t] = bfw[t]; }
    if (t == 0) sbb = bfb[0];
    __syncthreads();

    int p = blockIdx.x * blockDim.x + t;
    if (p >= PP) return;
    int s = src[p], d = dst[p];
    float a[16], bb[16];
    const float4* ap = (const float4*)(g_h1 + (size_t)s * 16);
    const float4* bp = (const float4*)(g_h1 + (size_t)d * 16);
#pragma unroll
    for (int i = 0; i < 4; i++) {
        float4 va = ap[i], vb = bp[i];
        a[i * 4 + 0] = va.x; a[i * 4 + 1] = va.y; a[i * 4 + 2] = va.z; a[i * 4 + 3] = va.w;
        bb[i * 4 + 0] = vb.x; bb[i * 4 + 1] = vb.y; bb[i * 4 + 2] = vb.z; bb[i * 4 + 3] = vb.w;
    }
    float v2[16];
#pragma unroll
    for (int j = 0; j < 16; j++) {
        float acc = sb2[j];
#pragma unroll
        for (int k = 0; k < 16; k++) acc += a[k] * sw2[k * 16 + j];
#pragma unroll
        for (int k = 0; k < 16; k++) acc += bb[k] * sw2[(16 + k) * 16 + j];
        v2[j] = acc > 0.0f ? acc : 0.0f;
    }
    float v3[8];
#pragma unroll
    for (int j = 0; j < 8; j++) {
        float acc = sb3[j];
#pragma unroll
        for (int k = 0; k < 16; k++) acc += v2[k] * sw3[k * 8 + j];
        v3[j] = acc > 0.0f ? acc : 0.0f;
    }
    float acc = sbb;
#pragma unroll
    for (int j = 0; j < 8; j++) acc += v3[j] * swb[j];
    out[p] = 1.0f / (1.0f + expf(-acc));
}

// ---------------------------------------------------------------------------
extern "C" void kernel_launch(void* const* d_in, const int* in_sizes, int n_in,
                              void* d_out, int out_size) {
    const float* x    = (const float*)d_in[0];
    const int*   eidx = (const int*)d_in[1];
    const int*   src  = (const int*)d_in[2];
    const int*   dst  = (const int*)d_in[3];
    const float* Wx   = (const float*)d_in[4];
    const float* bx   = (const float*)d_in[5];
    const float* Wh   = (const float*)d_in[6];
    const float* bh   = (const float*)d_in[7];
    const float* bg   = (const float*)d_in[8];
    const float* wc   = (const float*)d_in[9];
    const float* fc1w = (const float*)d_in[10];
    const float* fc1b = (const float*)d_in[11];
    const float* fc2w = (const float*)d_in[12];
    const float* fc2b = (const float*)d_in[13];
    const float* fc3w = (const float*)d_in[14];
    const float* fc3b = (const float*)d_in[15];
    const float* bfw  = (const float*)d_in[16];
    const float* bfb  = (const float*)d_in[17];
    float* out = (float*)d_out;

    (void)in_sizes; (void)n_in; (void)out_size;

    build_weights<<<(224 * 128 + 64 * 128 + 128 + 255) / 256, 256>>>(Wx, bx, Wh, bh, bg);
    zero_state<<<(NN * HIDN + 255) / 256, 256>>>();
    gemm128<<<(NN + 63) / 64, 256>>>(x, 0);   // Z0

    for (int t = 0; t < TT; t++) {
        const int* row = eidx + (size_t)t * 2 * EE;
        const int* col = row + EE;
        zero_counts<<<(NN + 255) / 256, 256>>>();
        histogram_kernel<<<(EE + 255) / 256, 256>>>(row, col);
        dis_kernel<<<(NN + 255) / 256, 256>>>();
        scan_kernel<<<1, 1024>>>();
        scatter_kernel<<<(EE + 255) / 256, 256>>>(row, col);
        gather_kernel<<<(NN + 7) / 8, 256>>>(x, 0);
        gather_kernel<<<(NN + 7) / 8, 256>>>(x, 1);
        gemm128<<<(NN + 63) / 64, 256>>>(x, 1);
        gates_kernel<<<(NN * HIDN + 255) / 256, 256>>>(wc);
    }

    h1_kernel<<<(NN * 16 + 255) / 256, 256>>>(fc1w, fc1b);
    pair_kernel<<<(PP + 255) / 256, 256>>>(src, dst, fc2w, fc2b, fc3w, fc3b, bfw, bfb, out);
}